// round 7
// baseline (speedup 1.0000x reference)
#include <cuda_runtime.h>
#include <cuda_fp16.h>
#include <cstdint>

#define NH       128
#define ET       128          // edges per CTA tile
#define THREADS  128          // 4 warps, 64x64 warp tiles

// ---------------- smem layout (bytes) ----------------
#define OFF_RIDX 0             // 128 ints
#define OFF_CIDX 512           // 128 ints
#define OFF_AHI  1024          // 128 rows x 256B (fp16 hi only)
#define OFF_BHI  (OFF_AHI + 32768)
#define OFF_BLO  (OFF_BHI + 32768)
#define SMEM_TOTAL (OFF_BLO + 32768)   // 99328 B -> 2 CTAs/SM

#define MAX_NODES 131072

// ---------------- device scratch (no allocs allowed) ----------------
__device__ uint4 g_xh[MAX_NODES * 16];    // [node][128] fp16 hi (16B chunks, linear)
__device__ uint4 g_wimg_hi[4][2048];      // B'[n][k] fp16, swizzled 32KB images
__device__ uint4 g_wimg_lo[4][2048];

// ---------------- helpers ----------------
__device__ __forceinline__ uint32_t smem_u32(const void* p) {
    uint32_t a;
    asm("{ .reg .u64 t; cvta.to.shared.u64 t, %1; cvt.u32.u64 %0, t; }" : "=r"(a) : "l"(p));
    return a;
}
__device__ __forceinline__ float frelu(float v) { return fmaxf(v, 0.0f); }

__device__ __forceinline__ uint32_t packh2(float a, float b) {
    __half2 h = __floats2half2_rn(a, b);
    return *reinterpret_cast<uint32_t*>(&h);
}

__device__ __forceinline__ void cp16(uint32_t smem_dst, const void* gsrc) {
    asm volatile("cp.async.cg.shared.global [%0], [%1], 16;"
                 :: "r"(smem_dst), "l"(gsrc) : "memory");
}

__device__ __forceinline__ void ldsm_x4(uint32_t (&r)[4], uint32_t addr) {
    asm volatile("ldmatrix.sync.aligned.m8n8.x4.shared.b16 {%0,%1,%2,%3}, [%4];"
        : "=r"(r[0]), "=r"(r[1]), "=r"(r[2]), "=r"(r[3]) : "r"(addr));
}
__device__ __forceinline__ void ldsm_x2(uint32_t (&r)[2], uint32_t addr) {
    asm volatile("ldmatrix.sync.aligned.m8n8.x2.shared.b16 {%0,%1}, [%2];"
        : "=r"(r[0]), "=r"(r[1]) : "r"(addr));
}
__device__ __forceinline__ void mma16816(float (&d)[4], const uint32_t (&a)[4],
                                         const uint32_t (&b)[2]) {
    asm volatile("mma.sync.aligned.m16n8k16.row.col.f32.f16.f16.f32 "
        "{%0,%1,%2,%3}, {%4,%5,%6,%7}, {%8,%9}, {%0,%1,%2,%3};"
        : "+f"(d[0]), "+f"(d[1]), "+f"(d[2]), "+f"(d[3])
        : "r"(a[0]), "r"(a[1]), "r"(a[2]), "r"(a[3]), "r"(b[0]), "r"(b[1]));
}

// ================= prep kernels =================
// B'[n][k] = W[k][n], row n = 256B, 16B chunk c placed at (c ^ (n&7))
__global__ void prep_w_kernel(const float* __restrict__ Wm, const float* __restrict__ We) {
    int idx = blockIdx.x * blockDim.x + threadIdx.x;   // < 4*16384
    if (idx >= 65536) return;
    int mat = idx >> 14, e = idx & 16383;
    int n = e >> 7, k = e & 127;
    float v = (mat < 3) ? Wm[(mat * 128 + k) * 128 + n] : We[k * 128 + n];
    __half hi = __float2half_rn(v);
    __half lo = __float2half_rn(v - __half2float(hi));
    uint32_t pos = (uint32_t)(n * 256 + (((k >> 3) ^ (n & 7)) << 4) + ((k & 7) << 1));
    *(__half*)((char*)g_wimg_hi[mat] + pos) = hi;
    *(__half*)((char*)g_wimg_lo[mat] + pos) = lo;
}

__global__ void prep_x_kernel(const float* __restrict__ x, long long total) {
    long long idx = (long long)blockIdx.x * blockDim.x + threadIdx.x;
    if (idx >= total) return;
    ((__half*)g_xh)[idx] = __float2half_rn(x[idx]);
}

// ===== warp GEMM: acc += A(128x128 fp16) @ (Bhi + Blo)^T, warp tile 64x64 =====
__device__ __forceinline__ void do_gemm(uint32_t sb, float (&acc)[4][8][4],
                                        int wm, int wn, int lane) {
    const int sx = lane & 7;
    const int aR = 64 * wm + sx + ((lane >> 3) & 1) * 8;
    const int aK = (lane >> 4) & 1;
    const int bR = 64 * wn + sx;
    const int bK = (lane >> 3) & 1;
    const uint32_t aBase = sb + OFF_AHI + (uint32_t)aR * 256;
    const uint32_t bBase = sb + OFF_BHI + (uint32_t)bR * 256;

    #pragma unroll 1
    for (int ks = 0; ks < 8; ks++) {
        uint32_t ah[4][4];
        #pragma unroll
        for (int mt = 0; mt < 4; mt++) {
            uint32_t off = (uint32_t)(mt * 16 * 256) + ((uint32_t)((2 * ks + aK) ^ sx) << 4);
            ldsm_x4(ah[mt], aBase + off);
        }
        #pragma unroll
        for (int nt = 0; nt < 8; nt++) {
            uint32_t off = (uint32_t)(nt * 8 * 256) + ((uint32_t)((2 * ks + bK) ^ sx) << 4);
            uint32_t bh[2], bl[2];
            ldsm_x2(bh, bBase + off);
            ldsm_x2(bl, bBase + off + (OFF_BLO - OFF_BHI));
            #pragma unroll
            for (int mt = 0; mt < 4; mt++) {
                mma16816(acc[mt][nt], ah[mt], bh);
                mma16816(acc[mt][nt], ah[mt], bl);
            }
        }
    }
}

// ================= main fused kernel =================
__global__ void __launch_bounds__(THREADS, 2)
edge_conv_mma(const float* __restrict__ eattr,
              const int*   __restrict__ eidx,
              const float* __restrict__ bm,
              const float* __restrict__ be,
              float* __restrict__ out,
              int E, int n_nodes)
{
    extern __shared__ char smc[];
    const uint32_t sb = smem_u32(smc);
    int* ridx = (int*)(smc + OFF_RIDX);
    int* cidx = (int*)(smc + OFF_CIDX);

    const int tid  = threadIdx.x;
    const int wid  = tid >> 5;
    const int lane = tid & 31;
    const int wm   = wid & 1;          // row group (64 edges)
    const int wn   = wid >> 1;         // col group (64 cols)
    const long long e0 = (long long)blockIdx.x * ET;

    {
        long long e = e0 + tid; if (e >= E) e = E - 1;
        int r = eidx[e];
        int c = eidx[(long long)E + e];
        ridx[tid] = min(max(r, 0), n_nodes - 1);
        cidx[tid] = min(max(c, 0), n_nodes - 1);
    }

    float acc[4][8][4];
    #pragma unroll
    for (int i = 0; i < 4; i++)
        #pragma unroll
        for (int j = 0; j < 8; j++)
            #pragma unroll
            for (int q = 0; q < 4; q++) acc[i][j][q] = 0.0f;

    // =========== GEMM 1: three K=128 segments ===========
    for (int seg = 0; seg < 3; seg++) {
        __syncthreads();   // prior A/B consumed; idx visible on seg 0
        // --- stage A tile (fp16 hi only, 2048 chunks) ---
        if (seg < 2) {
            const int* idxa = (seg == 0) ? ridx : cidx;
            #pragma unroll
            for (int it = 0; it < 16; it++) {
                int i = tid + it * THREADS;          // < 2048
                int e = i >> 4, c = i & 15;
                int node = idxa[e];
                uint32_t off = (uint32_t)(e * 256 + ((c ^ (e & 7)) << 4));
                cp16(sb + OFF_AHI + off, &g_xh[node * 16 + c]);
            }
        } else {
            #pragma unroll 4
            for (int it = 0; it < 16; it++) {
                int i = tid + it * THREADS;
                int e = i >> 4, c = i & 15;
                long long ge = e0 + e; if (ge >= E) ge = E - 1;
                const float4* s = (const float4*)(eattr + ge * NH + c * 8);
                float4 fa = __ldg(s), fb = __ldg(s + 1);
                uint4 h;
                h.x = packh2(fa.x, fa.y);
                h.y = packh2(fa.z, fa.w);
                h.z = packh2(fb.x, fb.y);
                h.w = packh2(fb.z, fb.w);
                uint32_t off = (uint32_t)(e * 256 + ((c ^ (e & 7)) << 4));
                *(uint4*)(smc + OFF_AHI + off) = h;
            }
        }
        // --- stage B tile (cp.async of preswizzled images) ---
        #pragma unroll
        for (int it = 0; it < 16; it++) {
            int i = tid + it * THREADS;              // < 2048
            cp16(sb + OFF_BHI + i * 16, &g_wimg_hi[seg][i]);
            cp16(sb + OFF_BLO + i * 16, &g_wimg_lo[seg][i]);
        }
        asm volatile("cp.async.commit_group;" ::: "memory");
        asm volatile("cp.async.wait_group 0;" ::: "memory");
        __syncthreads();
        do_gemm(sb, acc, wm, wn, lane);
    }

    __syncthreads();   // all warps done reading A/B of GEMM1

    // --- stage B = W_edge images (async; overlaps epilogue 1) ---
    #pragma unroll
    for (int it = 0; it < 16; it++) {
        int i = tid + it * THREADS;
        cp16(sb + OFF_BHI + i * 16, &g_wimg_hi[3][i]);
        cp16(sb + OFF_BLO + i * 16, &g_wimg_lo[3][i]);
    }
    asm volatile("cp.async.commit_group;" ::: "memory");

    // ==== epilogue 1: ea2 = eattr + relu(msg + bm), RMW A tile in place (fp16) ====
    {
        const int rq = lane >> 2;          // 0..7
        const int cq = (lane & 3) * 2;     // 0,2,4,6
        #pragma unroll
        for (int mt = 0; mt < 4; mt++) {
            int row0 = 64 * wm + 16 * mt + rq;
            #pragma unroll
            for (int nt = 0; nt < 8; nt++) {
                int c = 64 * wn + 8 * nt + cq;
                float2 bmv = __ldg((const float2*)(bm + c));
                #pragma unroll
                for (int h = 0; h < 2; h++) {
                    int row = row0 + 8 * h;
                    uint32_t addr = (uint32_t)(row * 256 +
                                    (((c >> 3) ^ (row & 7)) << 4) + ((c & 7) << 1));
                    uint32_t hu = *(uint32_t*)(smc + OFF_AHI + addr);
                    __half2 hb = *(__half2*)&hu;
                    float ev0 = __half2float(__low2half(hb));
                    float ev1 = __half2float(__high2half(hb));
                    float v0 = ev0 + frelu(acc[mt][nt][2 * h + 0] + bmv.x);
                    float v1 = ev1 + frelu(acc[mt][nt][2 * h + 1] + bmv.y);
                    *(uint32_t*)(smc + OFF_AHI + addr) = packh2(v0, v1);
                    acc[mt][nt][2 * h + 0] = 0.0f;
                    acc[mt][nt][2 * h + 1] = 0.0f;
                }
            }
        }
    }
    asm volatile("cp.async.wait_group 0;" ::: "memory");
    __syncthreads();   // ea2 tile + W_edge complete across warps

    // =========== GEMM 2 ===========
    do_gemm(sb, acc, wm, wn, lane);

    // =========== epilogue 2: out = relu(acc + be) ===========
    {
        const int rq = lane >> 2;
        const int cq = (lane & 3) * 2;
        #pragma unroll
        for (int mt = 0; mt < 4; mt++) {
            int row0 = 64 * wm + 16 * mt + rq;
            #pragma unroll
            for (int nt = 0; nt < 8; nt++) {
                int c = 64 * wn + 8 * nt + cq;
                float2 bev = __ldg((const float2*)(be + c));
                #pragma unroll
                for (int h = 0; h < 2; h++) {
                    int row = row0 + 8 * h;
                    long long ge = e0 + row;
                    if (ge < E) {
                        float2 o;
                        o.x = frelu(acc[mt][nt][2 * h + 0] + bev.x);
                        o.y = frelu(acc[mt][nt][2 * h + 1] + bev.y);
                        *(float2*)(out + ge * NH + c) = o;
                    }
                }
            }
        }
    }
}

// ================= host =================
extern "C" void kernel_launch(void* const* d_in, const int* in_sizes, int n_in,
                              void* d_out, int out_size)
{
    const float* x     = (const float*)d_in[0];
    const float* eattr = (const float*)d_in[1];
    const int*   eidx  = (const int*)d_in[2];   // int32 (JAX canonicalizes int64->int32)
    const float* Wm    = (const float*)d_in[3];
    const float* bm    = (const float*)d_in[4];
    const float* We    = (const float*)d_in[5];
    const float* be    = (const float*)d_in[6];
    float*       out   = (float*)d_out;

    const int E  = in_sizes[2] / 2;
    int n_nodes  = in_sizes[0] / NH;
    if (n_nodes > MAX_NODES) n_nodes = MAX_NODES;

    prep_w_kernel<<<(65536 + 255) / 256, 256>>>(Wm, We);
    long long xt = (long long)n_nodes * NH;
    prep_x_kernel<<<(unsigned)((xt + 255) / 256), 256>>>(x, xt);

    cudaFuncSetAttribute(edge_conv_mma,
                         cudaFuncAttributeMaxDynamicSharedMemorySize, SMEM_TOTAL);

    dim3 grid((E + ET - 1) / ET);
    edge_conv_mma<<<grid, THREADS, SMEM_TOTAL>>>(eattr, eidx, bm, be, out, E, n_nodes);
}

// round 8
// speedup vs baseline: 1.4407x; 1.4407x over previous
#include <cuda_runtime.h>
#include <cuda_fp16.h>
#include <cstdint>

#define NH       128
#define ET       128          // edges per CTA tile
#define THREADS  256          // 8 warps, 32x64 warp tiles

// ---------------- smem layout (bytes) ----------------
#define OFF_RIDX 0             // 128 ints
#define OFF_CIDX 512           // 128 ints
#define OFF_AHI  1024          // 128 rows x 256B (fp16)
#define OFF_B0   (OFF_AHI + 32768)
#define OFF_B1   (OFF_B0 + 32768)
#define SMEM_TOTAL (OFF_B1 + 32768)   // 99328 B -> 2 CTAs/SM

#define MAX_NODES 131072

// ---------------- device scratch (no allocs allowed) ----------------
__device__ uint4 g_xh[MAX_NODES * 16];    // [node][128] fp16 (16B chunks, linear)
__device__ uint4 g_wimg[4][2048];         // B'[n][k] fp16, swizzled 32KB images

// ---------------- helpers ----------------
__device__ __forceinline__ uint32_t smem_u32(const void* p) {
    uint32_t a;
    asm("{ .reg .u64 t; cvta.to.shared.u64 t, %1; cvt.u32.u64 %0, t; }" : "=r"(a) : "l"(p));
    return a;
}
__device__ __forceinline__ float frelu(float v) { return fmaxf(v, 0.0f); }

__device__ __forceinline__ uint32_t packh2(float a, float b) {
    __half2 h = __floats2half2_rn(a, b);
    return *reinterpret_cast<uint32_t*>(&h);
}

__device__ __forceinline__ void cp16(uint32_t smem_dst, const void* gsrc) {
    asm volatile("cp.async.cg.shared.global [%0], [%1], 16;"
                 :: "r"(smem_dst), "l"(gsrc) : "memory");
}
__device__ __forceinline__ void cp_commit() {
    asm volatile("cp.async.commit_group;" ::: "memory");
}
__device__ __forceinline__ void cp_wait1() {
    asm volatile("cp.async.wait_group 1;" ::: "memory");
}
__device__ __forceinline__ void cp_wait0() {
    asm volatile("cp.async.wait_group 0;" ::: "memory");
}

__device__ __forceinline__ void ldsm_x4(uint32_t (&r)[4], uint32_t addr) {
    asm volatile("ldmatrix.sync.aligned.m8n8.x4.shared.b16 {%0,%1,%2,%3}, [%4];"
        : "=r"(r[0]), "=r"(r[1]), "=r"(r[2]), "=r"(r[3]) : "r"(addr));
}
__device__ __forceinline__ void ldsm_x2(uint32_t (&r)[2], uint32_t addr) {
    asm volatile("ldmatrix.sync.aligned.m8n8.x2.shared.b16 {%0,%1}, [%2];"
        : "=r"(r[0]), "=r"(r[1]) : "r"(addr));
}
__device__ __forceinline__ void mma16816(float (&d)[4], const uint32_t (&a)[4],
                                         const uint32_t (&b)[2]) {
    asm volatile("mma.sync.aligned.m16n8k16.row.col.f32.f16.f16.f32 "
        "{%0,%1,%2,%3}, {%4,%5,%6,%7}, {%8,%9}, {%0,%1,%2,%3};"
        : "+f"(d[0]), "+f"(d[1]), "+f"(d[2]), "+f"(d[3])
        : "r"(a[0]), "r"(a[1]), "r"(a[2]), "r"(a[3]), "r"(b[0]), "r"(b[1]));
}

// ================= prep kernels =================
// B'[n][k] = W[k][n], row n = 256B, 16B chunk c placed at (c ^ (n&7))
__global__ void prep_w_kernel(const float* __restrict__ Wm, const float* __restrict__ We) {
    int idx = blockIdx.x * blockDim.x + threadIdx.x;   // < 4*16384
    if (idx >= 65536) return;
    int mat = idx >> 14, e = idx & 16383;
    int n = e >> 7, k = e & 127;
    float v = (mat < 3) ? Wm[(mat * 128 + k) * 128 + n] : We[k * 128 + n];
    uint32_t pos = (uint32_t)(n * 256 + (((k >> 3) ^ (n & 7)) << 4) + ((k & 7) << 1));
    *(__half*)((char*)g_wimg[mat] + pos) = __float2half_rn(v);
}

__global__ void prep_x_kernel(const float* __restrict__ x, long long total) {
    long long idx = (long long)blockIdx.x * blockDim.x + threadIdx.x;
    if (idx >= total) return;
    ((__half*)g_xh)[idx] = __float2half_rn(x[idx]);
}

// ===== warp GEMM: acc += A(128x128 fp16) @ B^T, warp tile 32x64, 1-term =====
__device__ __forceinline__ void do_gemm(uint32_t sb, uint32_t bOff,
                                        float (&acc)[2][8][4],
                                        int wm, int wn, int lane) {
    const int sx = lane & 7;
    const int aR = 32 * wm + sx + ((lane >> 3) & 1) * 8;
    const int aK = (lane >> 4) & 1;
    const int bR = 64 * wn + sx;
    const int bK = (lane >> 3) & 1;
    const uint32_t aBase = sb + OFF_AHI + (uint32_t)aR * 256;
    const uint32_t bBase = sb + bOff + (uint32_t)bR * 256;

    #pragma unroll 1
    for (int ks = 0; ks < 8; ks++) {
        uint32_t ah[2][4];
        #pragma unroll
        for (int mt = 0; mt < 2; mt++) {
            uint32_t off = (uint32_t)(mt * 16 * 256) + ((uint32_t)((2 * ks + aK) ^ sx) << 4);
            ldsm_x4(ah[mt], aBase + off);
        }
        #pragma unroll
        for (int nt = 0; nt < 8; nt++) {
            uint32_t off = (uint32_t)(nt * 8 * 256) + ((uint32_t)((2 * ks + bK) ^ sx) << 4);
            uint32_t bh[2];
            ldsm_x2(bh, bBase + off);
            #pragma unroll
            for (int mt = 0; mt < 2; mt++) {
                mma16816(acc[mt][nt], ah[mt], bh);
            }
        }
    }
}

// ================= main fused kernel =================
__global__ void __launch_bounds__(THREADS, 2)
edge_conv_mma(const float* __restrict__ eattr,
              const int*   __restrict__ eidx,
              const float* __restrict__ bm,
              const float* __restrict__ be,
              float* __restrict__ out,
              int E, int n_nodes)
{
    extern __shared__ char smc[];
    const uint32_t sb = smem_u32(smc);
    int* ridx = (int*)(smc + OFF_RIDX);
    int* cidx = (int*)(smc + OFF_CIDX);

    const int tid  = threadIdx.x;
    const int wid  = tid >> 5;
    const int lane = tid & 31;
    const int wm   = wid & 3;          // row group (32 edges)
    const int wn   = wid >> 2;         // col group (64 cols)
    const long long e0 = (long long)blockIdx.x * ET;

    // --- prefetch B(seg0) into buf0 (group 1) ---
    #pragma unroll
    for (int it = 0; it < 8; it++) {
        int i = tid + it * THREADS;              // < 2048
        cp16(sb + OFF_B0 + i * 16, &g_wimg[0][i]);
    }
    cp_commit();

    if (tid < ET) {
        long long e = e0 + tid; if (e >= E) e = E - 1;
        int r = eidx[e];
        int c = eidx[(long long)E + e];
        ridx[tid] = min(max(r, 0), n_nodes - 1);
        cidx[tid] = min(max(c, 0), n_nodes - 1);
    }
    __syncthreads();   // idx visible for gathers

    float acc[2][8][4];
    #pragma unroll
    for (int i = 0; i < 2; i++)
        #pragma unroll
        for (int j = 0; j < 8; j++)
            #pragma unroll
            for (int q = 0; q < 4; q++) acc[i][j][q] = 0.0f;

    // =========== GEMM 1: three K=128 segments, B double-buffered ===========
    // group order: B0 | A0 | B1 | A1 | B2 | B3   (A2 = plain sts)
    #pragma unroll 1
    for (int seg = 0; seg < 3; seg++) {
        // --- stage A tile (fp16, 2048 chunks) ---
        if (seg < 2) {
            const int* idxa = (seg == 0) ? ridx : cidx;
            #pragma unroll
            for (int it = 0; it < 8; it++) {
                int i = tid + it * THREADS;          // < 2048
                int e = i >> 4, c = i & 15;
                int node = idxa[e];
                uint32_t off = (uint32_t)(e * 256 + ((c ^ (e & 7)) << 4));
                cp16(sb + OFF_AHI + off, &g_xh[node * 16 + c]);
            }
            cp_commit();
        } else {
            #pragma unroll 4
            for (int it = 0; it < 8; it++) {
                int i = tid + it * THREADS;
                int e = i >> 4, c = i & 15;
                long long ge = e0 + e; if (ge >= E) ge = E - 1;
                const float4* s = (const float4*)(eattr + ge * NH + c * 8);
                float4 fa = __ldg(s), fb = __ldg(s + 1);
                uint4 h;
                h.x = packh2(fa.x, fa.y);
                h.y = packh2(fa.z, fa.w);
                h.z = packh2(fb.x, fb.y);
                h.w = packh2(fb.z, fb.w);
                uint32_t off = (uint32_t)(e * 256 + ((c ^ (e & 7)) << 4));
                *(uint4*)(smc + OFF_AHI + off) = h;
            }
        }
        // --- prefetch B(seg+1) into the other buffer ---
        {
            uint32_t nextOff = ((seg + 1) & 1) ? OFF_B1 : OFF_B0;
            #pragma unroll
            for (int it = 0; it < 8; it++) {
                int i = tid + it * THREADS;
                cp16(sb + nextOff + i * 16, &g_wimg[seg + 1][i]);
            }
            cp_commit();
        }
        cp_wait1();        // A(seg) + B(seg) done; B(seg+1) may fly
        __syncthreads();
        do_gemm(sb, (seg & 1) ? OFF_B1 : OFF_B0, acc, wm, wn, lane);
        __syncthreads();   // A consumed before next-seg restage
    }

    // ==== epilogue 1: ea2 = eattr + relu(msg + bm), RMW A tile in place (fp16) ====
    {
        const int rq = lane >> 2;          // 0..7
        const int cq = (lane & 3) * 2;     // 0,2,4,6
        #pragma unroll
        for (int mt = 0; mt < 2; mt++) {
            int row0 = 32 * wm + 16 * mt + rq;
            #pragma unroll
            for (int nt = 0; nt < 8; nt++) {
                int c = 64 * wn + 8 * nt + cq;
                float2 bmv = __ldg((const float2*)(bm + c));
                #pragma unroll
                for (int h = 0; h < 2; h++) {
                    int row = row0 + 8 * h;
                    uint32_t addr = (uint32_t)(row * 256 +
                                    (((c >> 3) ^ (row & 7)) << 4) + ((c & 7) << 1));
                    uint32_t hu = *(uint32_t*)(smc + OFF_AHI + addr);
                    __half2 hb = *(__half2*)&hu;
                    float ev0 = __half2float(__low2half(hb));
                    float ev1 = __half2float(__high2half(hb));
                    float v0 = ev0 + frelu(acc[mt][nt][2 * h + 0] + bmv.x);
                    float v1 = ev1 + frelu(acc[mt][nt][2 * h + 1] + bmv.y);
                    *(uint32_t*)(smc + OFF_AHI + addr) = packh2(v0, v1);
                    acc[mt][nt][2 * h + 0] = 0.0f;
                    acc[mt][nt][2 * h + 1] = 0.0f;
                }
            }
        }
    }
    cp_wait0();        // W_edge (B3, in buf1) landed
    __syncthreads();   // ea2 tile complete across warps

    // =========== GEMM 2 (B3 = W_edge in buf1) ===========
    do_gemm(sb, OFF_B1, acc, wm, wn, lane);

    // =========== epilogue 2: out = relu(acc + be) ===========
    {
        const int rq = lane >> 2;
        const int cq = (lane & 3) * 2;
        #pragma unroll
        for (int mt = 0; mt < 2; mt++) {
            int row0 = 32 * wm + 16 * mt + rq;
            #pragma unroll
            for (int nt = 0; nt < 8; nt++) {
                int c = 64 * wn + 8 * nt + cq;
                float2 bev = __ldg((const float2*)(be + c));
                #pragma unroll
                for (int h = 0; h < 2; h++) {
                    int row = row0 + 8 * h;
                    long long ge = e0 + row;
                    if (ge < E) {
                        float2 o;
                        o.x = frelu(acc[mt][nt][2 * h + 0] + bev.x);
                        o.y = frelu(acc[mt][nt][2 * h + 1] + bev.y);
                        *(float2*)(out + ge * NH + c) = o;
                    }
                }
            }
        }
    }
}

// ================= host =================
extern "C" void kernel_launch(void* const* d_in, const int* in_sizes, int n_in,
                              void* d_out, int out_size)
{
    const float* x     = (const float*)d_in[0];
    const float* eattr = (const float*)d_in[1];
    const int*   eidx  = (const int*)d_in[2];   // int32 (JAX canonicalizes int64->int32)
    const float* Wm    = (const float*)d_in[3];
    const float* bm    = (const float*)d_in[4];
    const float* We    = (const float*)d_in[5];
    const float* be    = (const float*)d_in[6];
    float*       out   = (float*)d_out;

    const int E  = in_sizes[2] / 2;
    int n_nodes  = in_sizes[0] / NH;
    if (n_nodes > MAX_NODES) n_nodes = MAX_NODES;

    prep_w_kernel<<<(65536 + 255) / 256, 256>>>(Wm, We);
    long long xt = (long long)n_nodes * NH;
    prep_x_kernel<<<(unsigned)((xt + 255) / 256), 256>>>(x, xt);

    cudaFuncSetAttribute(edge_conv_mma,
                         cudaFuncAttributeMaxDynamicSharedMemorySize, SMEM_TOTAL);

    dim3 grid((E + ET - 1) / ET);
    edge_conv_mma<<<grid, THREADS, SMEM_TOTAL>>>(eattr, eidx, bm, be, out, E, n_nodes);
}

// round 9
// speedup vs baseline: 1.4409x; 1.0001x over previous
#include <cuda_runtime.h>
#include <cuda_fp16.h>
#include <cstdint>

#define NH       128
#define ET       128          // edges per CTA tile
#define THREADS  256          // 8 warps, 32x64 warp tiles

// ---------------- smem layout (bytes) ----------------
#define OFF_RIDX 0             // 128 ints
#define OFF_CIDX 512           // 128 ints
#define OFF_AHI  1024          // 128 rows x 256B (fp16)
#define OFF_B0   (OFF_AHI + 32768)
#define OFF_B1   (OFF_B0 + 32768)
#define SMEM_TOTAL (OFF_B1 + 32768)   // 99328 B -> 2 CTAs/SM

#define MAX_NODES 131072

// ---------------- device scratch (no allocs allowed) ----------------
__device__ uint4 g_xh[MAX_NODES * 16];    // [node][128] fp16 (16B chunks, linear)
__device__ uint4 g_wimg[4][2048];         // B'[n][k] fp16, swizzled 32KB images

// ---------------- helpers ----------------
__device__ __forceinline__ uint32_t smem_u32(const void* p) {
    uint32_t a;
    asm("{ .reg .u64 t; cvta.to.shared.u64 t, %1; cvt.u32.u64 %0, t; }" : "=r"(a) : "l"(p));
    return a;
}
__device__ __forceinline__ float frelu(float v) { return fmaxf(v, 0.0f); }

__device__ __forceinline__ uint32_t packh2(float a, float b) {
    __half2 h = __floats2half2_rn(a, b);
    return *reinterpret_cast<uint32_t*>(&h);
}

__device__ __forceinline__ void cp16(uint32_t smem_dst, const void* gsrc) {
    asm volatile("cp.async.cg.shared.global [%0], [%1], 16;"
                 :: "r"(smem_dst), "l"(gsrc) : "memory");
}
__device__ __forceinline__ void cp_commit() {
    asm volatile("cp.async.commit_group;" ::: "memory");
}
__device__ __forceinline__ void cp_wait1() {
    asm volatile("cp.async.wait_group 1;" ::: "memory");
}
__device__ __forceinline__ void cp_wait0() {
    asm volatile("cp.async.wait_group 0;" ::: "memory");
}

__device__ __forceinline__ void ldsm_x4(uint32_t (&r)[4], uint32_t addr) {
    asm volatile("ldmatrix.sync.aligned.m8n8.x4.shared.b16 {%0,%1,%2,%3}, [%4];"
        : "=r"(r[0]), "=r"(r[1]), "=r"(r[2]), "=r"(r[3]) : "r"(addr));
}
__device__ __forceinline__ void ldsm_x2(uint32_t (&r)[2], uint32_t addr) {
    asm volatile("ldmatrix.sync.aligned.m8n8.x2.shared.b16 {%0,%1}, [%2];"
        : "=r"(r[0]), "=r"(r[1]) : "r"(addr));
}
__device__ __forceinline__ void mma16816(float (&d)[4], const uint32_t (&a)[4],
                                         const uint32_t (&b)[2]) {
    asm volatile("mma.sync.aligned.m16n8k16.row.col.f32.f16.f16.f32 "
        "{%0,%1,%2,%3}, {%4,%5,%6,%7}, {%8,%9}, {%0,%1,%2,%3};"
        : "+f"(d[0]), "+f"(d[1]), "+f"(d[2]), "+f"(d[3])
        : "r"(a[0]), "r"(a[1]), "r"(a[2]), "r"(a[3]), "r"(b[0]), "r"(b[1]));
}

// ================= prep kernels =================
// B'[n][k] = W[k][n], row n = 256B, 16B chunk c placed at (c ^ (n&7))
__global__ void prep_w_kernel(const float* __restrict__ Wm, const float* __restrict__ We) {
    int idx = blockIdx.x * blockDim.x + threadIdx.x;   // < 4*16384
    if (idx >= 65536) return;
    int mat = idx >> 14, e = idx & 16383;
    int n = e >> 7, k = e & 127;
    float v = (mat < 3) ? Wm[(mat * 128 + k) * 128 + n] : We[k * 128 + n];
    uint32_t pos = (uint32_t)(n * 256 + (((k >> 3) ^ (n & 7)) << 4) + ((k & 7) << 1));
    *(__half*)((char*)g_wimg[mat] + pos) = __float2half_rn(v);
}

__global__ void prep_x_kernel(const float* __restrict__ x, long long total) {
    long long idx = (long long)blockIdx.x * blockDim.x + threadIdx.x;
    if (idx >= total) return;
    ((__half*)g_xh)[idx] = __float2half_rn(x[idx]);
}

// ===== warp GEMM: acc += A(128x128 fp16) @ B^T, warp tile 32x64, 1-term =====
__device__ __forceinline__ void do_gemm(uint32_t sb, uint32_t bOff,
                                        float (&acc)[2][8][4],
                                        int wm, int wn, int lane) {
    const int sx = lane & 7;
    const int aR = 32 * wm + sx + ((lane >> 3) & 1) * 8;
    const int aK = (lane >> 4) & 1;
    const int bR = 64 * wn + sx;
    const int bK = (lane >> 3) & 1;
    const uint32_t aBase = sb + OFF_AHI + (uint32_t)aR * 256;
    const uint32_t bBase = sb + bOff + (uint32_t)bR * 256;

    #pragma unroll 1
    for (int ks = 0; ks < 8; ks++) {
        uint32_t ah[2][4];
        #pragma unroll
        for (int mt = 0; mt < 2; mt++) {
            uint32_t off = (uint32_t)(mt * 16 * 256) + ((uint32_t)((2 * ks + aK) ^ sx) << 4);
            ldsm_x4(ah[mt], aBase + off);
        }
        #pragma unroll
        for (int nt = 0; nt < 8; nt++) {
            uint32_t off = (uint32_t)(nt * 8 * 256) + ((uint32_t)((2 * ks + bK) ^ sx) << 4);
            uint32_t bh[2];
            ldsm_x2(bh, bBase + off);
            #pragma unroll
            for (int mt = 0; mt < 2; mt++) {
                mma16816(acc[mt][nt], ah[mt], bh);
            }
        }
    }
}

// ================= main fused kernel =================
__global__ void __launch_bounds__(THREADS, 2)
edge_conv_mma(const float* __restrict__ eattr,
              const int*   __restrict__ eidx,
              const float* __restrict__ bm,
              const float* __restrict__ be,
              float* __restrict__ out,
              int E, int n_nodes)
{
    extern __shared__ char smc[];
    const uint32_t sb = smem_u32(smc);
    int* ridx = (int*)(smc + OFF_RIDX);
    int* cidx = (int*)(smc + OFF_CIDX);

    const int tid  = threadIdx.x;
    const int wid  = tid >> 5;
    const int lane = tid & 31;
    const int wm   = wid & 3;          // row group (32 edges)
    const int wn   = wid >> 2;         // col group (64 cols)
    const long long e0 = (long long)blockIdx.x * ET;

    // --- prefetch B(seg0) into buf0 (group 1) ---
    #pragma unroll
    for (int it = 0; it < 8; it++) {
        int i = tid + it * THREADS;              // < 2048
        cp16(sb + OFF_B0 + i * 16, &g_wimg[0][i]);
    }
    cp_commit();

    if (tid < ET) {
        long long e = e0 + tid; if (e >= E) e = E - 1;
        int r = eidx[e];
        int c = eidx[(long long)E + e];
        ridx[tid] = min(max(r, 0), n_nodes - 1);
        cidx[tid] = min(max(c, 0), n_nodes - 1);
    }
    __syncthreads();   // idx visible for gathers

    float acc[2][8][4];
    #pragma unroll
    for (int i = 0; i < 2; i++)
        #pragma unroll
        for (int j = 0; j < 8; j++)
            #pragma unroll
            for (int q = 0; q < 4; q++) acc[i][j][q] = 0.0f;

    // =========== GEMM 1: three K=128 segments, B double-buffered ===========
    // group order: B0 | A0 | B1 | A1 | B2 | B3   (A2 = plain sts)
    #pragma unroll 1
    for (int seg = 0; seg < 3; seg++) {
        // --- stage A tile (fp16, 2048 chunks) ---
        if (seg < 2) {
            const int* idxa = (seg == 0) ? ridx : cidx;
            #pragma unroll
            for (int it = 0; it < 8; it++) {
                int i = tid + it * THREADS;          // < 2048
                int e = i >> 4, c = i & 15;
                int node = idxa[e];
                uint32_t off = (uint32_t)(e * 256 + ((c ^ (e & 7)) << 4));
                cp16(sb + OFF_AHI + off, &g_xh[node * 16 + c]);
            }
            cp_commit();
        } else {
            #pragma unroll 4
            for (int it = 0; it < 8; it++) {
                int i = tid + it * THREADS;
                int e = i >> 4, c = i & 15;
                long long ge = e0 + e; if (ge >= E) ge = E - 1;
                const float4* s = (const float4*)(eattr + ge * NH + c * 8);
                float4 fa = __ldg(s), fb = __ldg(s + 1);
                uint4 h;
                h.x = packh2(fa.x, fa.y);
                h.y = packh2(fa.z, fa.w);
                h.z = packh2(fb.x, fb.y);
                h.w = packh2(fb.z, fb.w);
                uint32_t off = (uint32_t)(e * 256 + ((c ^ (e & 7)) << 4));
                *(uint4*)(smc + OFF_AHI + off) = h;
            }
        }
        // --- prefetch B(seg+1) into the other buffer ---
        {
            uint32_t nextOff = ((seg + 1) & 1) ? OFF_B1 : OFF_B0;
            #pragma unroll
            for (int it = 0; it < 8; it++) {
                int i = tid + it * THREADS;
                cp16(sb + nextOff + i * 16, &g_wimg[seg + 1][i]);
            }
            cp_commit();
        }
        cp_wait1();        // A(seg) + B(seg) done; B(seg+1) may fly
        __syncthreads();
        do_gemm(sb, (seg & 1) ? OFF_B1 : OFF_B0, acc, wm, wn, lane);
        __syncthreads();   // A consumed before next-seg restage
    }

    // ==== epilogue 1: ea2 = eattr + relu(msg + bm), RMW A tile in place (fp16) ====
    {
        const int rq = lane >> 2;          // 0..7
        const int cq = (lane & 3) * 2;     // 0,2,4,6
        #pragma unroll
        for (int mt = 0; mt < 2; mt++) {
            int row0 = 32 * wm + 16 * mt + rq;
            #pragma unroll
            for (int nt = 0; nt < 8; nt++) {
                int c = 64 * wn + 8 * nt + cq;
                float2 bmv = __ldg((const float2*)(bm + c));
                #pragma unroll
                for (int h = 0; h < 2; h++) {
                    int row = row0 + 8 * h;
                    uint32_t addr = (uint32_t)(row * 256 +
                                    (((c >> 3) ^ (row & 7)) << 4) + ((c & 7) << 1));
                    uint32_t hu = *(uint32_t*)(smc + OFF_AHI + addr);
                    __half2 hb = *(__half2*)&hu;
                    float ev0 = __half2float(__low2half(hb));
                    float ev1 = __half2float(__high2half(hb));
                    float v0 = ev0 + frelu(acc[mt][nt][2 * h + 0] + bmv.x);
                    float v1 = ev1 + frelu(acc[mt][nt][2 * h + 1] + bmv.y);
                    *(uint32_t*)(smc + OFF_AHI + addr) = packh2(v0, v1);
                    acc[mt][nt][2 * h + 0] = 0.0f;
                    acc[mt][nt][2 * h + 1] = 0.0f;
                }
            }
        }
    }
    cp_wait0();        // W_edge (B3, in buf1) landed
    __syncthreads();   // ea2 tile complete across warps

    // =========== GEMM 2 (B3 = W_edge in buf1) ===========
    do_gemm(sb, OFF_B1, acc, wm, wn, lane);

    // =========== epilogue 2: out = relu(acc + be) ===========
    {
        const int rq = lane >> 2;
        const int cq = (lane & 3) * 2;
        #pragma unroll
        for (int mt = 0; mt < 2; mt++) {
            int row0 = 32 * wm + 16 * mt + rq;
            #pragma unroll
            for (int nt = 0; nt < 8; nt++) {
                int c = 64 * wn + 8 * nt + cq;
                float2 bev = __ldg((const float2*)(be + c));
                #pragma unroll
                for (int h = 0; h < 2; h++) {
                    int row = row0 + 8 * h;
                    long long ge = e0 + row;
                    if (ge < E) {
                        float2 o;
                        o.x = frelu(acc[mt][nt][2 * h + 0] + bev.x);
                        o.y = frelu(acc[mt][nt][2 * h + 1] + bev.y);
                        *(float2*)(out + ge * NH + c) = o;
                    }
                }
            }
        }
    }
}

// ================= host =================
extern "C" void kernel_launch(void* const* d_in, const int* in_sizes, int n_in,
                              void* d_out, int out_size)
{
    const float* x     = (const float*)d_in[0];
    const float* eattr = (const float*)d_in[1];
    const int*   eidx  = (const int*)d_in[2];   // int32 (JAX canonicalizes int64->int32)
    const float* Wm    = (const float*)d_in[3];
    const float* bm    = (const float*)d_in[4];
    const float* We    = (const float*)d_in[5];
    const float* be    = (const float*)d_in[6];
    float*       out   = (float*)d_out;

    const int E  = in_sizes[2] / 2;
    int n_nodes  = in_sizes[0] / NH;
    if (n_nodes > MAX_NODES) n_nodes = MAX_NODES;

    prep_w_kernel<<<(65536 + 255) / 256, 256>>>(Wm, We);
    long long xt = (long long)n_nodes * NH;
    prep_x_kernel<<<(unsigned)((xt + 255) / 256), 256>>>(x, xt);

    cudaFuncSetAttribute(edge_conv_mma,
                         cudaFuncAttributeMaxDynamicSharedMemorySize, SMEM_TOTAL);

    dim3 grid((E + ET - 1) / ET);
    edge_conv_mma<<<grid, THREADS, SMEM_TOTAL>>>(eattr, eidx, bm, be, out, E, n_nodes);
}